// round 6
// baseline (speedup 1.0000x reference)
#include <cuda_runtime.h>
#include <math.h>

#define NN   384
#define CC   128
#define HH   4
#define DHH  32
#define RR   96
#define SD   449
#define ZD   577     // CC + SD
#define MHH  256
#define HD   128     // HH*DHH
#define QT   32

// ---------------- scratch (device globals; no allocation allowed) ----------------
__device__ float g_xn[(size_t)NN * NN * CC];     // layernormed x  [i][j][c]
__device__ float g_zq[NN * ZD];                  // concat(mean1, s_inputs)
__device__ float g_zk[NN * ZD];                  // concat(mean0, s_inputs)
__device__ float g_h1[NN * MHH];
__device__ float g_h2[NN * MHH];
__device__ float g_qb[HH * NN * RR];             // [h][n][r]
__device__ float g_kb[HH * NN * RR];
__device__ float g_bias[(size_t)HH * NN * NN];   // [h][q][k]
__device__ float g_q[(size_t)NN * HH * NN * DHH]; // [i][h][j][d]
__device__ float g_k[(size_t)NN * HH * NN * DHH];
__device__ float g_v[(size_t)NN * HH * NN * DHH];
__device__ float g_gate[(size_t)NN * NN * CC];   // [i][j][c]
__device__ float g_o[(size_t)NN * NN * CC];      // [i][j][h*DH+d]

// ---------------- LayerNorm: one warp per (i,j) vector of 128 ----------------
__global__ void ln_kernel(const float* __restrict__ x,
                          const float* __restrict__ gamma,
                          const float* __restrict__ beta) {
    int w = threadIdx.x >> 5, lane = threadIdx.x & 31;
    size_t ij = (size_t)blockIdx.x * 4 + w;
    const float4 v4 = *(const float4*)(x + ij * CC + lane * 4);
    float s  = v4.x + v4.y + v4.z + v4.w;
    float s2 = v4.x * v4.x + v4.y * v4.y + v4.z * v4.z + v4.w * v4.w;
    #pragma unroll
    for (int o = 16; o > 0; o >>= 1) {
        s  += __shfl_xor_sync(0xffffffffu, s,  o);
        s2 += __shfl_xor_sync(0xffffffffu, s2, o);
    }
    float m   = s * (1.0f / CC);
    float var = s2 * (1.0f / CC) - m * m;
    float r   = rsqrtf(var + 1e-5f);
    float4 g4 = *(const float4*)(gamma + lane * 4);
    float4 b4 = *(const float4*)(beta  + lane * 4);
    float4 o4;
    o4.x = (v4.x - m) * r * g4.x + b4.x;
    o4.y = (v4.y - m) * r * g4.y + b4.y;
    o4.z = (v4.z - m) * r * g4.z + b4.z;
    o4.w = (v4.w - m) * r * g4.w + b4.w;
    *(float4*)(g_xn + ij * CC + lane * 4) = o4;
}

// ---------------- column means ----------------
__global__ void mean1_kernel() {   // mean over j -> g_zq[i][0:128]
    int i = blockIdx.x, c = threadIdx.x;
    const float* p = g_xn + (size_t)i * NN * CC + c;
    float s = 0.f;
    for (int j = 0; j < NN; j++) s += p[(size_t)j * CC];
    g_zq[i * ZD + c] = s * (1.0f / NN);
}
__global__ void mean0_kernel() {   // mean over i -> g_zk[j][0:128]
    int j = blockIdx.x, c = threadIdx.x;
    const float* p = g_xn + (size_t)j * CC + c;
    float s = 0.f;
    for (int i = 0; i < NN; i++) s += p[(size_t)i * NN * CC];
    g_zk[j * ZD + c] = s * (1.0f / NN);
}
__global__ void scopy_kernel(const float* __restrict__ s_inputs) {
    int n = blockIdx.x;
    for (int s = threadIdx.x; s < SD; s += blockDim.x) {
        float v = s_inputs[n * SD + s];
        g_zq[n * ZD + CC + s] = v;
        g_zk[n * ZD + CC + s] = v;
    }
}

// ---------------- small GEMM (bias MLPs): C = act(A[M,K] @ B[K,Nc]) ----------------
// mode 0: tanh, normal layout. mode 1: no act, head-transposed write to [h][n][r].
__global__ void small_gemm(const float* __restrict__ A, const float* __restrict__ B,
                           float* __restrict__ Cm, int M, int Nc, int K, int mode) {
    __shared__ float As[16][17], Bs[16][17];
    int row = blockIdx.y * 16 + threadIdx.y;
    int col = blockIdx.x * 16 + threadIdx.x;
    float acc = 0.f;
    for (int kt = 0; kt < K; kt += 16) {
        int ka = kt + threadIdx.x;
        As[threadIdx.y][threadIdx.x] = (row < M && ka < K) ? A[row * K + ka] : 0.f;
        int kb = kt + threadIdx.y;
        Bs[threadIdx.y][threadIdx.x] = (kb < K && col < Nc) ? B[kb * Nc + col] : 0.f;
        __syncthreads();
        #pragma unroll
        for (int kk = 0; kk < 16; kk++) acc += As[threadIdx.y][kk] * Bs[kk][threadIdx.x];
        __syncthreads();
    }
    if (row < M && col < Nc) {
        if (mode == 0) {
            Cm[row * Nc + col] = tanhf(acc);
        } else {
            int h = col / RR, r = col % RR;
            Cm[(h * NN + row) * RR + r] = acc;
        }
    }
}

// ---------------- low-rank bias: bias[h][q][k] = sum_r qb[h][q][r]*kb[h][k][r] ----------------
__global__ void bias_outer_kernel() {
    int h = blockIdx.z;
    int q = blockIdx.y * 16 + threadIdx.y;
    int k = blockIdx.x * 16 + threadIdx.x;
    __shared__ float Qs[16][17], Ks[16][17];
    const float* qb = g_qb + (size_t)h * NN * RR;
    const float* kb = g_kb + (size_t)h * NN * RR;
    float acc = 0.f;
    for (int rt = 0; rt < RR; rt += 16) {
        Qs[threadIdx.y][threadIdx.x] = qb[(blockIdx.y * 16 + threadIdx.y) * RR + rt + threadIdx.x];
        Ks[threadIdx.y][threadIdx.x] = kb[(blockIdx.x * 16 + threadIdx.y) * RR + rt + threadIdx.x];
        __syncthreads();
        #pragma unroll
        for (int kk = 0; kk < 16; kk++) acc += Qs[threadIdx.y][kk] * Ks[threadIdx.x][kk];
        __syncthreads();
    }
    g_bias[((size_t)h * NN + q) * NN + k] = acc;
}

// ---------------- big GEMM: [M=147456,128] @ [128,128], BM=BN=64, BK=16, 4x4/thread --------
// mode 0: q (scale 1/sqrt(32), head layout)  1: k (head layout)  2: v (head layout)
// mode 3: gate (sigmoid(v+bg), natural)      4: final (v+bo, natural -> out)
__global__ void big_gemm(const float* __restrict__ A, const float* __restrict__ A2,
                         const float* __restrict__ W, const float* __restrict__ bvec,
                         float* __restrict__ out, int mode) {
    __shared__ float As[64][20];   // [m][k] padded
    __shared__ float Bs[16][68];   // [k][n] padded (float4-aligned)
    int t = threadIdx.x;
    size_t m0 = (size_t)blockIdx.y * 64;
    int n0 = blockIdx.x * 64;
    int tx = t % 16, ty = t / 16;
    float acc[4][4];
    #pragma unroll
    for (int a = 0; a < 4; a++)
        #pragma unroll
        for (int b = 0; b < 4; b++) acc[a][b] = 0.f;

    for (int k0 = 0; k0 < CC; k0 += 16) {
        {   // A tile: thread -> row t/4, 4 k-cols
            size_t off = (m0 + t / 4) * CC + k0 + (t % 4) * 4;
            float4 av = *(const float4*)(A + off);
            if (A2) {
                float4 gv = *(const float4*)(A2 + off);
                av.x *= gv.x; av.y *= gv.y; av.z *= gv.z; av.w *= gv.w;
            }
            *(float4*)&As[t / 4][(t % 4) * 4] = av;
        }
        {   // B tile: thread -> k-row t/16, 4 n-cols
            float4 bv = *(const float4*)(W + (k0 + t / 16) * HD + n0 + (t % 16) * 4);
            *(float4*)&Bs[t / 16][(t % 16) * 4] = bv;
        }
        __syncthreads();
        #pragma unroll
        for (int kk = 0; kk < 16; kk++) {
            float a[4];
            #pragma unroll
            for (int u = 0; u < 4; u++) a[u] = As[ty * 4 + u][kk];
            float4 bv = *(float4*)&Bs[kk][tx * 4];
            #pragma unroll
            for (int u = 0; u < 4; u++) {
                acc[u][0] += a[u] * bv.x;
                acc[u][1] += a[u] * bv.y;
                acc[u][2] += a[u] * bv.z;
                acc[u][3] += a[u] * bv.w;
            }
        }
        __syncthreads();
    }

    const float qscale = 0.17677669529663687f;  // 1/sqrt(32)
    #pragma unroll
    for (int um = 0; um < 4; um++) {
        size_t m = m0 + ty * 4 + um;
        int i = (int)(m / NN), j = (int)(m % NN);
        #pragma unroll
        for (int un = 0; un < 4; un++) {
            int c = n0 + tx * 4 + un;
            float v = acc[um][un];
            if (mode <= 2) {
                int h = c / DHH, d = c % DHH;
                if (mode == 0) v *= qscale;
                out[(((size_t)i * HH + h) * NN + j) * DHH + d] = v;
            } else if (mode == 3) {
                v += bvec[c];
                out[m * CC + c] = 1.0f / (1.0f + __expf(-v));
            } else {
                out[m * CC + c] = v + bvec[c];
            }
        }
    }
}

// ---------------- attention: block per (q-tile of 32, head, row i) ----------------
__global__ void attn_kernel() {
    extern __shared__ float sm[];
    float* qs    = sm;                    // QT*33
    float* st    = qs + QT * 33;          // QT*385
    float* kvb   = st + QT * 385;         // 64*33 (K, padded) / 64*32 (V, float4)
    float* sminv = kvb + 64 * 33;         // QT

    int q0 = blockIdx.x * QT;
    int h  = blockIdx.y;
    int i  = blockIdx.z;
    int t  = threadIdx.x;

    size_t base = ((size_t)i * HH + h) * NN * DHH;
    const float* qg = g_q + base + (size_t)q0 * DHH;
    const float* kg = g_k + base;
    const float* vg = g_v + base;
    const float* biasrow = g_bias + (size_t)h * NN * NN;

    {   // load Q tile (padded stride 33)
        int r = t / 8, d4 = (t % 8) * 4;
        float4 v = *(const float4*)(qg + r * DHH + d4);
        float* dst = &qs[r * 33 + d4];
        dst[0] = v.x; dst[1] = v.y; dst[2] = v.z; dst[3] = v.w;
    }

    // -------- scores: thread handles column kk for 8 q-rows --------
    int kk  = t % 64;
    int qgp = t / 64;
    for (int kc = 0; kc < NN; kc += 64) {
        __syncthreads();
        #pragma unroll
        for (int l = 0; l < 2; l++) {       // stage K chunk [64][32] padded to stride 33
            int idx = t + l * 256;
            int r = idx / 8, d4 = (idx % 8) * 4;
            float4 v = *(const float4*)(kg + (size_t)(kc + r) * DHH + d4);
            float* dst = &kvb[r * 33 + d4];
            dst[0] = v.x; dst[1] = v.y; dst[2] = v.z; dst[3] = v.w;
        }
        __syncthreads();
        float kr[32];
        #pragma unroll
        for (int d = 0; d < 32; d++) kr[d] = kvb[kk * 33 + d];
        float acc[8];
        #pragma unroll
        for (int j = 0; j < 8; j++) acc[j] = 0.f;
        #pragma unroll
        for (int d = 0; d < 32; d++) {
            float kd = kr[d];
            #pragma unroll
            for (int j = 0; j < 8; j++) acc[j] += qs[(qgp * 8 + j) * 33 + d] * kd;
        }
        #pragma unroll
        for (int j = 0; j < 8; j++) {
            int qr = qgp * 8 + j;
            st[qr * 385 + kc + kk] = acc[j] + biasrow[(size_t)(q0 + qr) * NN + kc + kk];
        }
    }
    __syncthreads();

    // -------- softmax: warp w handles rows w*4..w*4+3 --------
    int warp = t / 32, lane = t % 32;
    for (int rr = 0; rr < 4; rr++) {
        int row = warp * 4 + rr;
        float vals[12];
        float mx = -1e30f;
        #pragma unroll
        for (int m = 0; m < 12; m++) {
            vals[m] = st[row * 385 + lane + m * 32];
            mx = fmaxf(mx, vals[m]);
        }
        #pragma unroll
        for (int o = 16; o > 0; o >>= 1) mx = fmaxf(mx, __shfl_xor_sync(0xffffffffu, mx, o));
        float s = 0.f;
        #pragma unroll
        for (int m = 0; m < 12; m++) {
            float p = __expf(vals[m] - mx);
            st[row * 385 + lane + m * 32] = p;
            s += p;
        }
        #pragma unroll
        for (int o = 16; o > 0; o >>= 1) s += __shfl_xor_sync(0xffffffffu, s, o);
        if (lane == 0) sminv[row] = 1.0f / s;
    }

    // -------- PV: thread handles (q-row t/8, 4 d-values) --------
    int qr = t / 8, dg = t % 8;
    float4 o4 = make_float4(0.f, 0.f, 0.f, 0.f);
    for (int kc = 0; kc < NN; kc += 64) {
        __syncthreads();
        ((float4*)kvb)[t]       = ((const float4*)(vg + (size_t)kc * DHH))[t];
        ((float4*)kvb)[t + 256] = ((const float4*)(vg + (size_t)kc * DHH))[t + 256];
        __syncthreads();
        #pragma unroll
        for (int k = 0; k < 64; k++) {
            float p = st[qr * 385 + kc + k];
            float4 vv = ((float4*)kvb)[k * 8 + dg];
            o4.x += p * vv.x; o4.y += p * vv.y; o4.z += p * vv.z; o4.w += p * vv.w;
        }
    }
    float inv = sminv[qr];
    o4.x *= inv; o4.y *= inv; o4.z *= inv; o4.w *= inv;
    *(float4*)(g_o + ((size_t)i * NN + q0 + qr) * CC + h * DHH + dg * 4) = o4;
}

// ---------------- launch ----------------
extern "C" void kernel_launch(void* const* d_in, const int* in_sizes, int n_in,
                              void* d_out, int out_size) {
    const float* x        = (const float*)d_in[0];
    const float* s_inputs = (const float*)d_in[1];
    const float* ln_gamma = (const float*)d_in[2];
    const float* ln_beta  = (const float*)d_in[3];
    const float* Wq1      = (const float*)d_in[4];
    const float* Wq2      = (const float*)d_in[5];
    const float* Wq3      = (const float*)d_in[6];
    const float* Wk1      = (const float*)d_in[7];
    const float* Wk2      = (const float*)d_in[8];
    const float* Wk3      = (const float*)d_in[9];
    const float* Wq_att   = (const float*)d_in[10];
    const float* Wk_att   = (const float*)d_in[11];
    const float* Wv_att   = (const float*)d_in[12];
    const float* Wg       = (const float*)d_in[13];
    const float* bg       = (const float*)d_in[14];
    const float* Wo       = (const float*)d_in[15];
    const float* bo       = (const float*)d_in[16];
    float* out = (float*)d_out;

    void *p_zq_v = nullptr, *p_zk_v = nullptr, *p_h1_v = nullptr, *p_h2_v = nullptr;
    void *p_qb_v = nullptr, *p_kb_v = nullptr;
    void *p_xn_v = nullptr, *p_q_v = nullptr, *p_k_v = nullptr, *p_v_v = nullptr;
    void *p_gate_v = nullptr, *p_o_v = nullptr;
    cudaGetSymbolAddress(&p_zq_v, g_zq);
    cudaGetSymbolAddress(&p_zk_v, g_zk);
    cudaGetSymbolAddress(&p_h1_v, g_h1);
    cudaGetSymbolAddress(&p_h2_v, g_h2);
    cudaGetSymbolAddress(&p_qb_v, g_qb);
    cudaGetSymbolAddress(&p_kb_v, g_kb);
    cudaGetSymbolAddress(&p_xn_v, g_xn);
    cudaGetSymbolAddress(&p_q_v, g_q);
    cudaGetSymbolAddress(&p_k_v, g_k);
    cudaGetSymbolAddress(&p_v_v, g_v);
    cudaGetSymbolAddress(&p_gate_v, g_gate);
    cudaGetSymbolAddress(&p_o_v, g_o);
    float* p_zq   = (float*)p_zq_v;
    float* p_zk   = (float*)p_zk_v;
    float* p_h1   = (float*)p_h1_v;
    float* p_h2   = (float*)p_h2_v;
    float* p_qb   = (float*)p_qb_v;
    float* p_kb   = (float*)p_kb_v;
    float* p_xn   = (float*)p_xn_v;
    float* p_q    = (float*)p_q_v;
    float* p_k    = (float*)p_k_v;
    float* p_v    = (float*)p_v_v;
    float* p_gate = (float*)p_gate_v;
    float* p_o    = (float*)p_o_v;

    // 1. LayerNorm
    ln_kernel<<<NN * NN / 4, 128>>>(x, ln_gamma, ln_beta);

    // 2. means + concat
    mean1_kernel<<<NN, CC>>>();
    mean0_kernel<<<NN, CC>>>();
    scopy_kernel<<<NN, 256>>>(s_inputs);

    // 3. bias MLPs
    dim3 tb(16, 16);
    small_gemm<<<dim3(MHH / 16, NN / 16), tb>>>(p_zq, Wq1, p_h1, NN, MHH, ZD, 0);
    small_gemm<<<dim3(MHH / 16, NN / 16), tb>>>(p_h1, Wq2, p_h2, NN, MHH, MHH, 0);
    small_gemm<<<dim3(HH * RR / 16, NN / 16), tb>>>(p_h2, Wq3, p_qb, NN, HH * RR, MHH, 1);
    small_gemm<<<dim3(MHH / 16, NN / 16), tb>>>(p_zk, Wk1, p_h1, NN, MHH, ZD, 0);
    small_gemm<<<dim3(MHH / 16, NN / 16), tb>>>(p_h1, Wk2, p_h2, NN, MHH, MHH, 0);
    small_gemm<<<dim3(HH * RR / 16, NN / 16), tb>>>(p_h2, Wk3, p_kb, NN, HH * RR, MHH, 1);

    // 4. low-rank bias matrix (precomputed once, shared by all rows)
    bias_outer_kernel<<<dim3(NN / 16, NN / 16, HH), tb>>>();

    // 5. projections
    dim3 gg(HD / 64, NN * NN / 64);
    big_gemm<<<gg, 256>>>(p_xn, nullptr, Wq_att, nullptr, p_q, 0);
    big_gemm<<<gg, 256>>>(p_xn, nullptr, Wk_att, nullptr, p_k, 1);
    big_gemm<<<gg, 256>>>(p_xn, nullptr, Wv_att, nullptr, p_v, 2);
    big_gemm<<<gg, 256>>>(p_xn, nullptr, Wg, bg, p_gate, 3);

    // 6. attention
    int smem = (QT * 33 + QT * 385 + 64 * 33 + QT) * sizeof(float);
    cudaFuncSetAttribute(attn_kernel, cudaFuncAttributeMaxDynamicSharedMemorySize, smem);
    attn_kernel<<<dim3(NN / QT, HH, NN), 256, smem>>>();

    // 7. gated output projection
    big_gemm<<<gg, 256>>>(p_o, p_gate, Wo, bo, out, 4);
}

// round 9
// speedup vs baseline: 1.0761x; 1.0761x over previous
#include <cuda_runtime.h>
#include <math.h>
#include <stdint.h>

#define NN   384
#define CC   128
#define HH   4
#define DHH  32
#define RR   96
#define SD   449
#define ZD   577     // CC + SD
#define MHH  256
#define HD   128     // HH*DHH
#define QT   32

#define AS_S 132     // As row stride (floats): bank = (4m+k)%32 -> conflict-free frag loads
#define WS_S 136     // Ws row stride (floats): bank = (8k+n)%32 -> conflict-free frag loads

// ---------------- scratch (device globals; no allocation allowed) ----------------
__device__ float g_xn[(size_t)NN * NN * CC];     // layernormed x  [i][j][c]
__device__ float g_zq[NN * ZD];                  // concat(mean1, s_inputs)
__device__ float g_zk[NN * ZD];                  // concat(mean0, s_inputs)
__device__ float g_h1[NN * MHH];
__device__ float g_h2[NN * MHH];
__device__ float g_qb[HH * NN * RR];             // [h][n][r]
__device__ float g_kb[HH * NN * RR];
__device__ float g_bias[(size_t)HH * NN * NN];   // [h][q][k]
__device__ float g_q[(size_t)NN * HH * NN * DHH]; // [i][h][j][d]
__device__ float g_k[(size_t)NN * HH * NN * DHH];
__device__ float g_v[(size_t)NN * HH * NN * DHH];
__device__ float g_gate[(size_t)NN * NN * CC];   // [i][j][c]
__device__ float g_o[(size_t)NN * NN * CC];      // [i][j][h*DH+d]

// ---------------- LayerNorm: one warp per (i,j) vector of 128 ----------------
__global__ void ln_kernel(const float* __restrict__ x,
                          const float* __restrict__ gamma,
                          const float* __restrict__ beta) {
    int w = threadIdx.x >> 5, lane = threadIdx.x & 31;
    size_t ij = (size_t)blockIdx.x * 4 + w;
    const float4 v4 = *(const float4*)(x + ij * CC + lane * 4);
    float s  = v4.x + v4.y + v4.z + v4.w;
    float s2 = v4.x * v4.x + v4.y * v4.y + v4.z * v4.z + v4.w * v4.w;
    #pragma unroll
    for (int o = 16; o > 0; o >>= 1) {
        s  += __shfl_xor_sync(0xffffffffu, s,  o);
        s2 += __shfl_xor_sync(0xffffffffu, s2, o);
    }
    float m   = s * (1.0f / CC);
    float var = s2 * (1.0f / CC) - m * m;
    float r   = rsqrtf(var + 1e-5f);
    float4 g4 = *(const float4*)(gamma + lane * 4);
    float4 b4 = *(const float4*)(beta  + lane * 4);
    float4 o4;
    o4.x = (v4.x - m) * r * g4.x + b4.x;
    o4.y = (v4.y - m) * r * g4.y + b4.y;
    o4.z = (v4.z - m) * r * g4.z + b4.z;
    o4.w = (v4.w - m) * r * g4.w + b4.w;
    *(float4*)(g_xn + ij * CC + lane * 4) = o4;
}

// ---------------- column means ----------------
__global__ void mean1_kernel() {   // mean over j -> g_zq[i][0:128]
    int i = blockIdx.x, c = threadIdx.x;
    const float* p = g_xn + (size_t)i * NN * CC + c;
    float s = 0.f;
    for (int j = 0; j < NN; j++) s += p[(size_t)j * CC];
    g_zq[i * ZD + c] = s * (1.0f / NN);
}
__global__ void mean0_kernel() {   // mean over i -> g_zk[j][0:128]
    int j = blockIdx.x, c = threadIdx.x;
    const float* p = g_xn + (size_t)j * CC + c;
    float s = 0.f;
    for (int i = 0; i < NN; i++) s += p[(size_t)i * NN * CC];
    g_zk[j * ZD + c] = s * (1.0f / NN);
}
__global__ void scopy_kernel(const float* __restrict__ s_inputs) {
    int n = blockIdx.x;
    for (int s = threadIdx.x; s < SD; s += blockDim.x) {
        float v = s_inputs[n * SD + s];
        g_zq[n * ZD + CC + s] = v;
        g_zk[n * ZD + CC + s] = v;
    }
}

// ---------------- small GEMM (bias MLPs): C = act(A[M,K] @ B[K,Nc]) ----------------
__global__ void small_gemm(const float* __restrict__ A, const float* __restrict__ B,
                           float* __restrict__ Cm, int M, int Nc, int K, int mode) {
    __shared__ float As[16][17], Bs[16][17];
    int row = blockIdx.y * 16 + threadIdx.y;
    int col = blockIdx.x * 16 + threadIdx.x;
    float acc = 0.f;
    for (int kt = 0; kt < K; kt += 16) {
        int ka = kt + threadIdx.x;
        As[threadIdx.y][threadIdx.x] = (row < M && ka < K) ? A[row * K + ka] : 0.f;
        int kb = kt + threadIdx.y;
        Bs[threadIdx.y][threadIdx.x] = (kb < K && col < Nc) ? B[kb * Nc + col] : 0.f;
        __syncthreads();
        #pragma unroll
        for (int kk = 0; kk < 16; kk++) acc += As[threadIdx.y][kk] * Bs[kk][threadIdx.x];
        __syncthreads();
    }
    if (row < M && col < Nc) {
        if (mode == 0) {
            Cm[row * Nc + col] = tanhf(acc);
        } else {
            int h = col / RR, r = col % RR;
            Cm[(h * NN + row) * RR + r] = acc;
        }
    }
}

// ---------------- low-rank bias: bias[h][q][k] = sum_r qb[h][q][r]*kb[h][k][r] ----------------
__global__ void bias_outer_kernel() {
    int h = blockIdx.z;
    int q = blockIdx.y * 16 + threadIdx.y;
    int k = blockIdx.x * 16 + threadIdx.x;
    __shared__ float Qs[16][17], Ks[16][17];
    const float* qb = g_qb + (size_t)h * NN * RR;
    const float* kb = g_kb + (size_t)h * NN * RR;
    float acc = 0.f;
    for (int rt = 0; rt < RR; rt += 16) {
        Qs[threadIdx.y][threadIdx.x] = qb[(blockIdx.y * 16 + threadIdx.y) * RR + rt + threadIdx.x];
        Ks[threadIdx.y][threadIdx.x] = kb[(blockIdx.x * 16 + threadIdx.y) * RR + rt + threadIdx.x];
        __syncthreads();
        #pragma unroll
        for (int kk = 0; kk < 16; kk++) acc += Qs[threadIdx.y][kk] * Ks[threadIdx.x][kk];
        __syncthreads();
    }
    g_bias[((size_t)h * NN + q) * NN + k] = acc;
}

// ---------------- tensor-core GEMM (3xTF32): [M,128] @ [128,128] ----------------
// Block: 128 M-rows x full N=128, K=128 fully staged in smem. 8 warps, warp tile 32x64.
// mode 0: q (scale, head layout)  1: k  2: v  3: gate (sigmoid+bg)  4: final (+bo)
__device__ __forceinline__ void tf32_split(float a, uint32_t& hi, uint32_t& lo) {
    uint32_t b = __float_as_uint(a);
    hi = b & 0xFFFFE000u;                     // tf32 truncation (matches HW read)
    lo = __float_as_uint(a - __uint_as_float(hi));
}

#define MMA_TF32(acc, a, b)                                                     \
    asm volatile("mma.sync.aligned.m16n8k8.row.col.f32.tf32.tf32.f32 "          \
                 "{%0,%1,%2,%3}, {%4,%5,%6,%7}, {%8,%9}, {%0,%1,%2,%3};\n"      \
                 : "+f"((acc)[0]), "+f"((acc)[1]), "+f"((acc)[2]), "+f"((acc)[3]) \
                 : "r"((a)[0]), "r"((a)[1]), "r"((a)[2]), "r"((a)[3]),          \
                   "r"((b)[0]), "r"((b)[1]))

__global__ void __launch_bounds__(256) tc_gemm(const float* __restrict__ A,
                                               const float* __restrict__ A2,
                                               const float* __restrict__ W,
                                               const float* __restrict__ bvec,
                                               float* __restrict__ out, int mode) {
    extern __shared__ float sh[];
    float* As = sh;                     // [128][AS_S]
    float* Ws = sh + 128 * AS_S;        // [128][WS_S], k-major: Ws[k*WS_S+n]
    int t = threadIdx.x;
    size_t m0 = (size_t)blockIdx.x * 128;

    #pragma unroll
    for (int l = 0; l < 16; l++) {      // W: 128x128, 16 float4 per thread
        int lin = t + l * 256;
        int k  = lin >> 5;
        int n4 = (lin & 31) << 2;
        float4 w4 = *(const float4*)(W + k * HD + n4);
        float* dst = Ws + k * WS_S + n4;
        dst[0] = w4.x; dst[1] = w4.y; dst[2] = w4.z; dst[3] = w4.w;
    }
    #pragma unroll
    for (int l = 0; l < 16; l++) {      // A tile 128x128 (fused gate mult if A2)
        int lin = t + l * 256;
        int m  = lin >> 5;
        int k4 = (lin & 31) << 2;
        size_t off = (m0 + m) * CC + k4;
        float4 a4 = *(const float4*)(A + off);
        if (A2) {
            float4 g4 = *(const float4*)(A2 + off);
            a4.x *= g4.x; a4.y *= g4.y; a4.z *= g4.z; a4.w *= g4.w;
        }
        float* dst = As + m * AS_S + k4;
        dst[0] = a4.x; dst[1] = a4.y; dst[2] = a4.z; dst[3] = a4.w;
    }
    __syncthreads();

    int wid = t >> 5, lane = t & 31;
    int wm = (wid >> 1) * 32, wn = (wid & 1) * 64;
    int lr = lane >> 2, lc = lane & 3;

    float acc[2][8][4];
    #pragma unroll
    for (int a = 0; a < 2; a++)
        #pragma unroll
        for (int b = 0; b < 8; b++)
            #pragma unroll
            for (int e = 0; e < 4; e++) acc[a][b][e] = 0.f;

    for (int k0 = 0; k0 < CC; k0 += 8) {
        uint32_t ahi[2][4], alo[2][4];
        #pragma unroll
        for (int tm = 0; tm < 2; tm++) {
            int r0 = wm + tm * 16 + lr;
            float a0 = As[r0 * AS_S + k0 + lc];
            float a1 = As[(r0 + 8) * AS_S + k0 + lc];
            float a2 = As[r0 * AS_S + k0 + lc + 4];
            float a3 = As[(r0 + 8) * AS_S + k0 + lc + 4];
            tf32_split(a0, ahi[tm][0], alo[tm][0]);
            tf32_split(a1, ahi[tm][1], alo[tm][1]);
            tf32_split(a2, ahi[tm][2], alo[tm][2]);
            tf32_split(a3, ahi[tm][3], alo[tm][3]);
        }
        uint32_t bhi[8][2], blo[8][2];
        #pragma unroll
        for (int tn = 0; tn < 8; tn++) {
            int n = wn + tn * 8 + lr;
            float b0 = Ws[(k0 + lc) * WS_S + n];
            float b1 = Ws[(k0 + lc + 4) * WS_S + n];
            tf32_split(b0, bhi[tn][0], blo[tn][0]);
            tf32_split(b1, bhi[tn][1], blo[tn][1]);
        }
        #pragma unroll
        for (int tm = 0; tm < 2; tm++)
            #pragma unroll
            for (int tn = 0; tn < 8; tn++) {
                MMA_TF32(acc[tm][tn], ahi[tm], bhi[tn]);
                MMA_TF32(acc[tm][tn], ahi[tm], blo[tn]);
                MMA_TF32(acc[tm][tn], alo[tm], bhi[tn]);
            }
    }

    const float qscale = 0.17677669529663687f;  // 1/sqrt(32)
    #pragma unroll
    for (int tm = 0; tm < 2; tm++) {
        #pragma unroll
        for (int tn = 0; tn < 8; tn++) {
            #pragma unroll
            for (int e = 0; e < 4; e++) {
                int row = wm + tm * 16 + lr + ((e >> 1) ? 8 : 0);
                int col = wn + tn * 8 + lc * 2 + (e & 1);
                size_t m = m0 + row;
                float v = acc[tm][tn][e];
                if (mode <= 2) {
                    int i = (int)(m / NN), j = (int)(m % NN);
                    int h = col / DHH, d = col % DHH;
                    if (mode == 0) v *= qscale;
                    out[(((size_t)i * HH + h) * NN + j) * DHH + d] = v;
                } else if (mode == 3) {
                    v += bvec[col];
                    out[m * CC + col] = 1.0f / (1.0f + __expf(-v));
                } else {
                    out[m * CC + col] = v + bvec[col];
                }
            }
        }
    }
}

// ---------------- attention: block per (q-tile of 32, head, row i) ----------------
__global__ void attn_kernel() {
    extern __shared__ float sm[];
    float* qs    = sm;                    // QT*33
    float* st    = qs + QT * 33;          // QT*385
    float* kvb   = st + QT * 385;         // 64*33 (K, padded) / 64*32 (V, float4)
    float* sminv = kvb + 64 * 33;         // QT

    int q0 = blockIdx.x * QT;
    int h  = blockIdx.y;
    int i  = blockIdx.z;
    int t  = threadIdx.x;

    size_t base = ((size_t)i * HH + h) * NN * DHH;
    const float* qg = g_q + base + (size_t)q0 * DHH;
    const float* kg = g_k + base;
    const float* vg = g_v + base;
    const float* biasrow = g_bias + (size_t)h * NN * NN;

    {   // load Q tile (padded stride 33)
        int r = t / 8, d4 = (t % 8) * 4;
        float4 v = *(const float4*)(qg + r * DHH + d4);
        float* dst = &qs[r * 33 + d4];
        dst[0] = v.x; dst[1] = v.y; dst[2] = v.z; dst[3] = v.w;
    }

    int kk  = t % 64;
    int qgp = t / 64;
    for (int kc = 0; kc < NN; kc += 64) {
        __syncthreads();
        #pragma unroll
        for (int l = 0; l < 2; l++) {
            int idx = t + l * 256;
            int r = idx / 8, d4 = (idx % 8) * 4;
            float4 v = *(const float4*)(kg + (size_t)(kc + r) * DHH + d4);
            float* dst = &kvb[r * 33 + d4];
            dst[0] = v.x; dst[1] = v.y; dst[2] = v.z; dst[3] = v.w;
        }
        __syncthreads();
        float kr[32];
        #pragma unroll
        for (int d = 0; d < 32; d++) kr[d] = kvb[kk * 33 + d];
        float acc[8];
        #pragma unroll
        for (int j = 0; j < 8; j++) acc[j] = 0.f;
        #pragma unroll
        for (int d = 0; d < 32; d++) {
            float kd = kr[d];
            #pragma unroll
            for (int j = 0; j < 8; j++) acc[j] += qs[(qgp * 8 + j) * 33 + d] * kd;
        }
        #pragma unroll
        for (int j = 0; j < 8; j++) {
            int qr = qgp * 8 + j;
            st[qr * 385 + kc + kk] = acc[j] + biasrow[(size_t)(q0 + qr) * NN + kc + kk];
        }
    }
    __syncthreads();

    int warp = t / 32, lane = t % 32;
    for (int rr = 0; rr < 4; rr++) {
        int row = warp * 4 + rr;
        float vals[12];
        float mx = -1e30f;
        #pragma unroll
        for (int m = 0; m < 12; m++) {
            vals[m] = st[row * 385 + lane + m * 32];
            mx = fmaxf(mx, vals[m]);
        }
        #pragma unroll
        for (int o = 16; o > 0; o >>= 1) mx = fmaxf(mx, __shfl_xor_sync(0xffffffffu, mx, o));
        float s = 0.f;
        #pragma unroll
        for (int m = 0; m < 12; m++) {
            float p = __expf(vals[m] - mx);
            st[row * 385 + lane + m * 32] = p;
            s += p;
        }
        #pragma unroll
        for (int o = 16; o > 0; o >>= 1) s += __shfl_xor_sync(0xffffffffu, s, o);
        if (lane == 0) sminv[row] = 1.0f / s;
    }

    int qr = t / 8, dg = t % 8;
    float4 o4 = make_float4(0.f, 0.f, 0.f, 0.f);
    for (int kc = 0; kc < NN; kc += 64) {
        __syncthreads();
        ((float4*)kvb)[t]       = ((const float4*)(vg + (size_t)kc * DHH))[t];
        ((float4*)kvb)[t + 256] = ((const float4*)(vg + (size_t)kc * DHH))[t + 256];
        __syncthreads();
        #pragma unroll
        for (int k = 0; k < 64; k++) {
            float p = st[qr * 385 + kc + k];
            float4 vv = ((float4*)kvb)[k * 8 + dg];
            o4.x += p * vv.x; o4.y += p * vv.y; o4.z += p * vv.z; o4.w += p * vv.w;
        }
    }
    float inv = sminv[qr];
    o4.x *= inv; o4.y *= inv; o4.z *= inv; o4.w *= inv;
    *(float4*)(g_o + ((size_t)i * NN + q0 + qr) * CC + h * DHH + dg * 4) = o4;
}

// ---------------- launch ----------------
extern "C" void kernel_launch(void* const* d_in, const int* in_sizes, int n_in,
                              void* d_out, int out_size) {
    const float* x        = (const float*)d_in[0];
    const float* s_inputs = (const float*)d_in[1];
    const float* ln_gamma = (const float*)d_in[2];
    const float* ln_beta  = (const float*)d_in[3];
    const float* Wq1      = (const float*)d_in[4];
    const float* Wq2      = (const float*)d_in[5];
    const float* Wq3      = (const float*)d_in[6];
    const float* Wk1      = (const float*)d_in[7];
    const float* Wk2      = (const float*)d_in[8];
    const float* Wk3      = (const float*)d_in[9];
    const float* Wq_att   = (const float*)d_in[10];
    const float* Wk_att   = (const float*)d_in[11];
    const float* Wv_att   = (const float*)d_in[12];
    const float* Wg       = (const float*)d_in[13];
    const float* bg       = (const float*)d_in[14];
    const float* Wo       = (const float*)d_in[15];
    const float* bo       = (const float*)d_in[16];
    float* out = (float*)d_out;

    void *p_zq_v = nullptr, *p_zk_v = nullptr, *p_h1_v = nullptr, *p_h2_v = nullptr;
    void *p_qb_v = nullptr, *p_kb_v = nullptr;
    void *p_xn_v = nullptr, *p_q_v = nullptr, *p_k_v = nullptr, *p_v_v = nullptr;
    void *p_gate_v = nullptr, *p_o_v = nullptr;
    cudaGetSymbolAddress(&p_zq_v, g_zq);
    cudaGetSymbolAddress(&p_zk_v, g_zk);
    cudaGetSymbolAddress(&p_h1_v, g_h1);
    cudaGetSymbolAddress(&p_h2_v, g_h2);
    cudaGetSymbolAddress(&p_qb_v, g_qb);
    cudaGetSymbolAddress(&p_kb_v, g_kb);
    cudaGetSymbolAddress(&p_xn_v, g_xn);
    cudaGetSymbolAddress(&p_q_v, g_q);
    cudaGetSymbolAddress(&p_k_v, g_k);
    cudaGetSymbolAddress(&p_v_v, g_v);
    cudaGetSymbolAddress(&p_gate_v, g_gate);
    cudaGetSymbolAddress(&p_o_v, g_o);
    float* p_zq   = (float*)p_zq_v;
    float* p_zk   = (float*)p_zk_v;
    float* p_h1   = (float*)p_h1_v;
    float* p_h2   = (float*)p_h2_v;
    float* p_qb   = (float*)p_qb_v;
    float* p_kb   = (float*)p_kb_v;
    float* p_xn   = (float*)p_xn_v;
    float* p_q    = (float*)p_q_v;
    float* p_k    = (float*)p_k_v;
    float* p_v    = (float*)p_v_v;
    float* p_gate = (float*)p_gate_v;
    float* p_o    = (float*)p_o_v;

    // 1. LayerNorm
    ln_kernel<<<NN * NN / 4, 128>>>(x, ln_gamma, ln_beta);

    // 2. means + concat
    mean1_kernel<<<NN, CC>>>();
    mean0_kernel<<<NN, CC>>>();
    scopy_kernel<<<NN, 256>>>(s_inputs);

    // 3. bias MLPs
    dim3 tb(16, 16);
    small_gemm<<<dim3(MHH / 16, NN / 16), tb>>>(p_zq, Wq1, p_h1, NN, MHH, ZD, 0);
    small_gemm<<<dim3(MHH / 16, NN / 16), tb>>>(p_h1, Wq2, p_h2, NN, MHH, MHH, 0);
    small_gemm<<<dim3(HH * RR / 16, NN / 16), tb>>>(p_h2, Wq3, p_qb, NN, HH * RR, MHH, 1);
    small_gemm<<<dim3(MHH / 16, NN / 16), tb>>>(p_zk, Wk1, p_h1, NN, MHH, ZD, 0);
    small_gemm<<<dim3(MHH / 16, NN / 16), tb>>>(p_h1, Wk2, p_h2, NN, MHH, MHH, 0);
    small_gemm<<<dim3(HH * RR / 16, NN / 16), tb>>>(p_h2, Wk3, p_kb, NN, HH * RR, MHH, 1);

    // 4. low-rank bias matrix
    bias_outer_kernel<<<dim3(NN / 16, NN / 16, HH), tb>>>();

    // 5. projections on tensor cores (3xTF32)
    int gsmem = (128 * AS_S + 128 * WS_S) * sizeof(float);   // ~137 KB
    cudaFuncSetAttribute(tc_gemm, cudaFuncAttributeMaxDynamicSharedMemorySize, gsmem);
    int gblocks = NN * NN / 128;   // 1152
    tc_gemm<<<gblocks, 256, gsmem>>>(p_xn, nullptr, Wq_att, nullptr, p_q, 0);
    tc_gemm<<<gblocks, 256, gsmem>>>(p_xn, nullptr, Wk_att, nullptr, p_k, 1);
    tc_gemm<<<gblocks, 256, gsmem>>>(p_xn, nullptr, Wv_att, nullptr, p_v, 2);
    tc_gemm<<<gblocks, 256, gsmem>>>(p_xn, nullptr, Wg, bg, p_gate, 3);

    // 6. attention
    int smem = (QT * 33 + QT * 385 + 64 * 33 + QT) * sizeof(float);
    cudaFuncSetAttribute(attn_kernel, cudaFuncAttributeMaxDynamicSharedMemorySize, smem);
    attn_kernel<<<dim3(NN / QT, HH, NN), 256, smem>>>();

    // 7. gated output projection (tensor cores, gate fused into A load)
    tc_gemm<<<gblocks, 256, gsmem>>>(p_o, p_gate, Wo, bo, out, 4);
}

// round 13
// speedup vs baseline: 1.6662x; 1.5483x over previous
#include <cuda_runtime.h>
#include <math.h>
#include <stdint.h>

#define NN   384
#define CC   128
#define HH   4
#define DHH  32
#define RR   96
#define SD   449
#define ZD   577     // CC + SD
#define MHH  256
#define HD   128     // HH*DHH

#define AS_S 132     // tc_gemm As row stride
#define WS_S 136     // tc_gemm Ws row stride
#define ST_S 388     // attn scores row stride (388 % 32 == 4 -> conflict-free frag loads)

// ---------------- scratch (device globals; no allocation allowed) ----------------
__device__ float g_xn[(size_t)NN * NN * CC];     // layernormed x  [i][j][c]
__device__ float g_zq[NN * ZD];                  // concat(mean1, s_inputs)
__device__ float g_zk[NN * ZD];                  // concat(mean0, s_inputs)
__device__ float g_h1[NN * MHH];
__device__ float g_h2[NN * MHH];
__device__ float g_qb[HH * NN * RR];             // [h][n][r]
__device__ float g_kb[HH * NN * RR];
__device__ float g_bias[(size_t)HH * NN * NN];   // [h][q][k]
__device__ float g_q[(size_t)NN * HH * NN * DHH]; // [i][h][j][d]
__device__ float g_k[(size_t)NN * HH * NN * DHH];
__device__ float g_v[(size_t)NN * HH * NN * DHH];
__device__ float g_gate[(size_t)NN * NN * CC];   // [i][j][c]
__device__ float g_o[(size_t)NN * NN * CC];      // [i][j][h*DH+d]

// ---------------- LayerNorm: one warp per (i,j) vector of 128 ----------------
__global__ void ln_kernel(const float* __restrict__ x,
                          const float* __restrict__ gamma,
                          const float* __restrict__ beta) {
    int w = threadIdx.x >> 5, lane = threadIdx.x & 31;
    size_t ij = (size_t)blockIdx.x * 4 + w;
    const float4 v4 = *(const float4*)(x + ij * CC + lane * 4);
    float s  = v4.x + v4.y + v4.z + v4.w;
    float s2 = v4.x * v4.x + v4.y * v4.y + v4.z * v4.z + v4.w * v4.w;
    #pragma unroll
    for (int o = 16; o > 0; o >>= 1) {
        s  += __shfl_xor_sync(0xffffffffu, s,  o);
        s2 += __shfl_xor_sync(0xffffffffu, s2, o);
    }
    float m   = s * (1.0f / CC);
    float var = s2 * (1.0f / CC) - m * m;
    float r   = rsqrtf(var + 1e-5f);
    float4 g4 = *(const float4*)(gamma + lane * 4);
    float4 b4 = *(const float4*)(beta  + lane * 4);
    float4 o4;
    o4.x = (v4.x - m) * r * g4.x + b4.x;
    o4.y = (v4.y - m) * r * g4.y + b4.y;
    o4.z = (v4.z - m) * r * g4.z + b4.z;
    o4.w = (v4.w - m) * r * g4.w + b4.w;
    *(float4*)(g_xn + ij * CC + lane * 4) = o4;
}

// ---------------- column means ----------------
__global__ void mean1_kernel() {   // mean over j -> g_zq[i][0:128]
    int i = blockIdx.x, c = threadIdx.x;
    const float* p = g_xn + (size_t)i * NN * CC + c;
    float s = 0.f;
    #pragma unroll 8
    for (int j = 0; j < NN; j++) s += p[(size_t)j * CC];
    g_zq[i * ZD + c] = s * (1.0f / NN);
}
__global__ void mean0_kernel() {   // mean over i -> g_zk[j][0:128]
    int j = blockIdx.x, c = threadIdx.x;
    const float* p = g_xn + (size_t)j * CC + c;
    float s = 0.f;
    #pragma unroll 8
    for (int i = 0; i < NN; i++) s += p[(size_t)i * NN * CC];
    g_zk[j * ZD + c] = s * (1.0f / NN);
}
__global__ void scopy_kernel(const float* __restrict__ s_inputs) {
    int n = blockIdx.x;
    for (int s = threadIdx.x; s < SD; s += blockDim.x) {
        float v = s_inputs[n * SD + s];
        g_zq[n * ZD + CC + s] = v;
        g_zk[n * ZD + CC + s] = v;
    }
}

// ---------------- small GEMM (bias MLPs): C = act(A[M,K] @ B[K,Nc]) ----------------
__global__ void small_gemm(const float* __restrict__ A, const float* __restrict__ B,
                           float* __restrict__ Cm, int M, int Nc, int K, int mode) {
    __shared__ float As[16][17], Bs[16][17];
    int row = blockIdx.y * 16 + threadIdx.y;
    int col = blockIdx.x * 16 + threadIdx.x;
    float acc = 0.f;
    for (int kt = 0; kt < K; kt += 16) {
        int ka = kt + threadIdx.x;
        As[threadIdx.y][threadIdx.x] = (row < M && ka < K) ? A[row * K + ka] : 0.f;
        int kb = kt + threadIdx.y;
        Bs[threadIdx.y][threadIdx.x] = (kb < K && col < Nc) ? B[kb * Nc + col] : 0.f;
        __syncthreads();
        #pragma unroll
        for (int kk = 0; kk < 16; kk++) acc += As[threadIdx.y][kk] * Bs[kk][threadIdx.x];
        __syncthreads();
    }
    if (row < M && col < Nc) {
        if (mode == 0) {
            Cm[row * Nc + col] = tanhf(acc);
        } else {
            int h = col / RR, r = col % RR;
            Cm[(h * NN + row) * RR + r] = acc;
        }
    }
}

// ---------------- low-rank bias: bias[h][q][k] = sum_r qb[h][q][r]*kb[h][k][r] ----------------
__global__ void bias_outer_kernel() {
    int h = blockIdx.z;
    int q = blockIdx.y * 16 + threadIdx.y;
    int k = blockIdx.x * 16 + threadIdx.x;
    __shared__ float Qs[16][17], Ks[16][17];
    const float* qb = g_qb + (size_t)h * NN * RR;
    const float* kb = g_kb + (size_t)h * NN * RR;
    float acc = 0.f;
    for (int rt = 0; rt < RR; rt += 16) {
        Qs[threadIdx.y][threadIdx.x] = qb[(blockIdx.y * 16 + threadIdx.y) * RR + rt + threadIdx.x];
        Ks[threadIdx.y][threadIdx.x] = kb[(blockIdx.x * 16 + threadIdx.y) * RR + rt + threadIdx.x];
        __syncthreads();
        #pragma unroll
        for (int kk = 0; kk < 16; kk++) acc += Qs[threadIdx.y][kk] * Ks[threadIdx.x][kk];
        __syncthreads();
    }
    g_bias[((size_t)h * NN + q) * NN + k] = acc;
}

// ---------------- 3xTF32 helpers ----------------
__device__ __forceinline__ void tf32_split(float a, uint32_t& hi, uint32_t& lo) {
    uint32_t b = __float_as_uint(a);
    hi = b & 0xFFFFE000u;                     // tf32 truncation (matches HW read)
    lo = __float_as_uint(a - __uint_as_float(hi));
}

#define MMA_TF32(acc, a, b)                                                     \
    asm volatile("mma.sync.aligned.m16n8k8.row.col.f32.tf32.tf32.f32 "          \
                 "{%0,%1,%2,%3}, {%4,%5,%6,%7}, {%8,%9}, {%0,%1,%2,%3};\n"      \
                 : "+f"((acc)[0]), "+f"((acc)[1]), "+f"((acc)[2]), "+f"((acc)[3]) \
                 : "r"((a)[0]), "r"((a)[1]), "r"((a)[2]), "r"((a)[3]),          \
                   "r"((b)[0]), "r"((b)[1]))

// ---------------- tensor-core GEMM (3xTF32): [M,128] @ [128,128] ----------------
__global__ void __launch_bounds__(256) tc_gemm(const float* __restrict__ A,
                                               const float* __restrict__ A2,
                                               const float* __restrict__ W,
                                               const float* __restrict__ bvec,
                                               float* __restrict__ out, int mode) {
    extern __shared__ float sh[];
    float* As = sh;                     // [128][AS_S]
    float* Ws = sh + 128 * AS_S;        // [128][WS_S], k-major: Ws[k*WS_S+n]
    int t = threadIdx.x;
    size_t m0 = (size_t)blockIdx.x * 128;

    #pragma unroll
    for (int l = 0; l < 16; l++) {
        int lin = t + l * 256;
        int k  = lin >> 5;
        int n4 = (lin & 31) << 2;
        float4 w4 = *(const float4*)(W + k * HD + n4);
        float* dst = Ws + k * WS_S + n4;
        dst[0] = w4.x; dst[1] = w4.y; dst[2] = w4.z; dst[3] = w4.w;
    }
    #pragma unroll
    for (int l = 0; l < 16; l++) {
        int lin = t + l * 256;
        int m  = lin >> 5;
        int k4 = (lin & 31) << 2;
        size_t off = (m0 + m) * CC + k4;
        float4 a4 = *(const float4*)(A + off);
        if (A2) {
            float4 g4 = *(const float4*)(A2 + off);
            a4.x *= g4.x; a4.y *= g4.y; a4.z *= g4.z; a4.w *= g4.w;
        }
        float* dst = As + m * AS_S + k4;
        dst[0] = a4.x; dst[1] = a4.y; dst[2] = a4.z; dst[3] = a4.w;
    }
    __syncthreads();

    int wid = t >> 5, lane = t & 31;
    int wm = (wid >> 1) * 32, wn = (wid & 1) * 64;
    int lr = lane >> 2, lc = lane & 3;

    float acc[2][8][4];
    #pragma unroll
    for (int a = 0; a < 2; a++)
        #pragma unroll
        for (int b = 0; b < 8; b++)
            #pragma unroll
            for (int e = 0; e < 4; e++) acc[a][b][e] = 0.f;

    for (int k0 = 0; k0 < CC; k0 += 8) {
        uint32_t ahi[2][4], alo[2][4];
        #pragma unroll
        for (int tm = 0; tm < 2; tm++) {
            int r0 = wm + tm * 16 + lr;
            tf32_split(As[r0 * AS_S + k0 + lc],           ahi[tm][0], alo[tm][0]);
            tf32_split(As[(r0 + 8) * AS_S + k0 + lc],     ahi[tm][1], alo[tm][1]);
            tf32_split(As[r0 * AS_S + k0 + lc + 4],       ahi[tm][2], alo[tm][2]);
            tf32_split(As[(r0 + 8) * AS_S + k0 + lc + 4], ahi[tm][3], alo[tm][3]);
        }
        uint32_t bhi[8][2], blo[8][2];
        #pragma unroll
        for (int tn = 0; tn < 8; tn++) {
            int n = wn + tn * 8 + lr;
            tf32_split(Ws[(k0 + lc) * WS_S + n],     bhi[tn][0], blo[tn][0]);
            tf32_split(Ws[(k0 + lc + 4) * WS_S + n], bhi[tn][1], blo[tn][1]);
        }
        #pragma unroll
        for (int tm = 0; tm < 2; tm++)
            #pragma unroll
            for (int tn = 0; tn < 8; tn++) {
                MMA_TF32(acc[tm][tn], ahi[tm], bhi[tn]);
                MMA_TF32(acc[tm][tn], ahi[tm], blo[tn]);
                MMA_TF32(acc[tm][tn], alo[tm], bhi[tn]);
            }
    }

    const float qscale = 0.17677669529663687f;  // 1/sqrt(32)
    #pragma unroll
    for (int tm = 0; tm < 2; tm++) {
        #pragma unroll
        for (int tn = 0; tn < 8; tn++) {
            #pragma unroll
            for (int e = 0; e < 4; e++) {
                int row = wm + tm * 16 + lr + ((e >> 1) ? 8 : 0);
                int col = wn + tn * 8 + lc * 2 + (e & 1);
                size_t m = m0 + row;
                float v = acc[tm][tn][e];
                if (mode <= 2) {
                    int i = (int)(m / NN), j = (int)(m % NN);
                    int h = col / DHH, d = col % DHH;
                    if (mode == 0) v *= qscale;
                    out[(((size_t)i * HH + h) * NN + j) * DHH + d] = v;
                } else if (mode == 3) {
                    v += bvec[col];
                    out[m * CC + col] = 1.0f / (1.0f + __expf(-v));
                } else {
                    out[m * CC + col] = v + bvec[col];
                }
            }
        }
    }
}

// ---------------- tensor-core attention: block per (64-q-tile, head, row i) ----------------
// Phase 1: scores = Q K^T (3xTF32) -> smem st. Softmax (+bias from gmem, L2-resident).
// Phase 2: O = P V (3xTF32), normalized in epilogue.
__global__ void __launch_bounds__(256) attn_tc_kernel() {
    extern __shared__ float sm[];
    float* st    = sm;                 // [64][ST_S]
    float* kvb   = st + 64 * ST_S;     // [64][33] staging for Q, K, V chunks
    float* sminv = kvb + 64 * 33;      // [64]

    int q0 = blockIdx.x * 64;
    int h  = blockIdx.y;
    int i  = blockIdx.z;
    int t  = threadIdx.x;
    int wid = t >> 5, lane = t & 31;
    int lr = lane >> 2, lc = lane & 3;

    size_t base = ((size_t)i * HH + h) * NN * DHH;
    const float* qg = g_q + base + (size_t)q0 * DHH;
    const float* kg = g_k + base;
    const float* vg = g_v + base;
    const float* biasrow = g_bias + (size_t)h * NN * NN;

    // ---- stage Q (64x32) into kvb, then pull A-fragments into registers ----
    #pragma unroll
    for (int l = 0; l < 2; l++) {
        int idx = t + l * 256;
        int r = idx >> 3, d4 = (idx & 7) << 2;
        float4 v = *(const float4*)(qg + (size_t)r * DHH + d4);
        float* dst = &kvb[r * 33 + d4];
        dst[0] = v.x; dst[1] = v.y; dst[2] = v.z; dst[3] = v.w;
    }
    __syncthreads();

    int wr = wid >> 1;        // q sub-tile (4 x 16 rows)
    int wc = wid & 1;         // phase1: k-col half (2 x 32); phase2: d half (2 x 16)
    uint32_t qhi[4][4], qlo[4][4];
    {
        int r0 = wr * 16 + lr;
        #pragma unroll
        for (int ks = 0; ks < 4; ks++) {
            tf32_split(kvb[r0 * 33 + ks * 8 + lc],           qhi[ks][0], qlo[ks][0]);
            tf32_split(kvb[(r0 + 8) * 33 + ks * 8 + lc],     qhi[ks][1], qlo[ks][1]);
            tf32_split(kvb[r0 * 33 + ks * 8 + lc + 4],       qhi[ks][2], qlo[ks][2]);
            tf32_split(kvb[(r0 + 8) * 33 + ks * 8 + lc + 4], qhi[ks][3], qlo[ks][3]);
        }
    }

    // ---- phase 1: scores ----
    for (int kc = 0; kc < NN; kc += 64) {
        __syncthreads();
        #pragma unroll
        for (int l = 0; l < 2; l++) {      // stage K chunk [64][32] -> stride 33
            int idx = t + l * 256;
            int r = idx >> 3, d4 = (idx & 7) << 2;
            float4 v = *(const float4*)(kg + (size_t)(kc + r) * DHH + d4);
            float* dst = &kvb[r * 33 + d4];
            dst[0] = v.x; dst[1] = v.y; dst[2] = v.z; dst[3] = v.w;
        }
        __syncthreads();
        float acc[4][4];
        #pragma unroll
        for (int tn = 0; tn < 4; tn++)
            #pragma unroll
            for (int e = 0; e < 4; e++) acc[tn][e] = 0.f;
        #pragma unroll
        for (int ks = 0; ks < 4; ks++) {
            #pragma unroll
            for (int tn = 0; tn < 4; tn++) {
                int n = wc * 32 + tn * 8 + lr;
                uint32_t bhi[2], blo[2];
                tf32_split(kvb[n * 33 + ks * 8 + lc],     bhi[0], blo[0]);
                tf32_split(kvb[n * 33 + ks * 8 + lc + 4], bhi[1], blo[1]);
                MMA_TF32(acc[tn], qhi[ks], bhi);
                MMA_TF32(acc[tn], qhi[ks], blo);
                MMA_TF32(acc[tn], qlo[ks], bhi);
            }
        }
        #pragma unroll
        for (int tn = 0; tn < 4; tn++)
            #pragma unroll
            for (int e = 0; e < 4; e++) {
                int row = wr * 16 + lr + ((e >> 1) ? 8 : 0);
                int col = kc + wc * 32 + tn * 8 + lc * 2 + (e & 1);
                st[row * ST_S + col] = acc[tn][e];
            }
    }
    __syncthreads();

    // ---- softmax over 384 cols (bias fused in; warp handles 8 rows) ----
    #pragma unroll
    for (int rr = 0; rr < 8; rr++) {
        int row = wid * 8 + rr;
        const float* brow = biasrow + (size_t)(q0 + row) * NN;
        float vals[12];
        float mx = -1e30f;
        #pragma unroll
        for (int m = 0; m < 12; m++) {
            vals[m] = st[row * ST_S + lane + m * 32] + brow[lane + m * 32];
            mx = fmaxf(mx, vals[m]);
        }
        #pragma unroll
        for (int o = 16; o > 0; o >>= 1) mx = fmaxf(mx, __shfl_xor_sync(0xffffffffu, mx, o));
        float s = 0.f;
        #pragma unroll
        for (int m = 0; m < 12; m++) {
            float p = __expf(vals[m] - mx);
            st[row * ST_S + lane + m * 32] = p;
            s += p;
        }
        #pragma unroll
        for (int o = 16; o > 0; o >>= 1) s += __shfl_xor_sync(0xffffffffu, s, o);
        if (lane == 0) sminv[row] = 1.0f / s;
    }

    // ---- phase 2: O = P V ----
    float oacc[2][4];
    #pragma unroll
    for (int tn = 0; tn < 2; tn++)
        #pragma unroll
        for (int e = 0; e < 4; e++) oacc[tn][e] = 0.f;

    for (int kc = 0; kc < NN; kc += 64) {
        __syncthreads();
        #pragma unroll
        for (int l = 0; l < 2; l++) {      // stage V chunk [64][32] -> stride 33
            int idx = t + l * 256;
            int r = idx >> 3, d4 = (idx & 7) << 2;
            float4 v = *(const float4*)(vg + (size_t)(kc + r) * DHH + d4);
            float* dst = &kvb[r * 33 + d4];
            dst[0] = v.x; dst[1] = v.y; dst[2] = v.z; dst[3] = v.w;
        }
        __syncthreads();
        int r0 = wr * 16 + lr;
        #pragma unroll
        for (int ks = 0; ks < 8; ks++) {
            uint32_t ahi[4], alo[4];
            int k0 = kc + ks * 8;
            tf32_split(st[r0 * ST_S + k0 + lc],           ahi[0], alo[0]);
            tf32_split(st[(r0 + 8) * ST_S + k0 + lc],     ahi[1], alo[1]);
            tf32_split(st[r0 * ST_S + k0 + lc + 4],       ahi[2], alo[2]);
            tf32_split(st[(r0 + 8) * ST_S + k0 + lc + 4], ahi[3], alo[3]);
            #pragma unroll
            for (int tn = 0; tn < 2; tn++) {
                int n = wc * 16 + tn * 8 + lr;
                uint32_t bhi[2], blo[2];
                tf32_split(kvb[(ks * 8 + lc) * 33 + n],     bhi[0], blo[0]);
                tf32_split(kvb[(ks * 8 + lc + 4) * 33 + n], bhi[1], blo[1]);
                MMA_TF32(oacc[tn], ahi, bhi);
                MMA_TF32(oacc[tn], ahi, blo);
                MMA_TF32(oacc[tn], alo, bhi);
            }
        }
    }

    #pragma unroll
    for (int tn = 0; tn < 2; tn++)
        #pragma unroll
        for (int e = 0; e < 4; e++) {
            int row = wr * 16 + lr + ((e >> 1) ? 8 : 0);
            int d   = wc * 16 + tn * 8 + lc * 2 + (e & 1);
            g_o[((size_t)i * NN + q0 + row) * CC + h * DHH + d] = oacc[tn][e] * sminv[row];
        }
}

// ---------------- launch ----------------
extern "C" void kernel_launch(void* const* d_in, const int* in_sizes, int n_in,
                              void* d_out, int out_size) {
    const float* x        = (const float*)d_in[0];
    const float* s_inputs = (const float*)d_in[1];
    const float* ln_gamma = (const float*)d_in[2];
    const float* ln_beta  = (const float*)d_in[3];
    const float* Wq1      = (const float*)d_in[4];
    const float* Wq2      = (const float*)d_in[5];
    const float* Wq3      = (const float*)d_in[6];
    const float* Wk1      = (const float*)d_in[7];
    const float* Wk2      = (const float*)d_in[8];
    const float* Wk3      = (const float*)d_in[9];
    const float* Wq_att   = (const float*)d_in[10];
    const float* Wk_att   = (const float*)d_in[11];
    const float* Wv_att   = (const float*)d_in[12];
    const float* Wg       = (const float*)d_in[13];
    const float* bg       = (const float*)d_in[14];
    const float* Wo       = (const float*)d_in[15];
    const float* bo       = (const float*)d_in[16];
    float* out = (float*)d_out;

    void *p_zq_v = nullptr, *p_zk_v = nullptr, *p_h1_v = nullptr, *p_h2_v = nullptr;
    void *p_qb_v = nullptr, *p_kb_v = nullptr;
    void *p_xn_v = nullptr, *p_q_v = nullptr, *p_k_v = nullptr, *p_v_v = nullptr;
    void *p_gate_v = nullptr, *p_o_v = nullptr;
    cudaGetSymbolAddress(&p_zq_v, g_zq);
    cudaGetSymbolAddress(&p_zk_v, g_zk);
    cudaGetSymbolAddress(&p_h1_v, g_h1);
    cudaGetSymbolAddress(&p_h2_v, g_h2);
    cudaGetSymbolAddress(&p_qb_v, g_qb);
    cudaGetSymbolAddress(&p_kb_v, g_kb);
    cudaGetSymbolAddress(&p_xn_v, g_xn);
    cudaGetSymbolAddress(&p_q_v, g_q);
    cudaGetSymbolAddress(&p_k_v, g_k);
    cudaGetSymbolAddress(&p_v_v, g_v);
    cudaGetSymbolAddress(&p_gate_v, g_gate);
    cudaGetSymbolAddress(&p_o_v, g_o);
    float* p_zq   = (float*)p_zq_v;
    float* p_zk   = (float*)p_zk_v;
    float* p_h1   = (float*)p_h1_v;
    float* p_h2   = (float*)p_h2_v;
    float* p_qb   = (float*)p_qb_v;
    float* p_kb   = (float*)p_kb_v;
    float* p_xn   = (float*)p_xn_v;
    float* p_q    = (float*)p_q_v;
    float* p_k    = (float*)p_k_v;
    float* p_v    = (float*)p_v_v;
    float* p_gate = (float*)p_gate_v;
    float* p_o    = (float*)p_o_v;

    // 1. LayerNorm
    ln_kernel<<<NN * NN / 4, 128>>>(x, ln_gamma, ln_beta);

    // 2. means + concat
    mean1_kernel<<<NN, CC>>>();
    mean0_kernel<<<NN, CC>>>();
    scopy_kernel<<<NN, 256>>>(s_inputs);

    // 3. bias MLPs
    dim3 tb(16, 16);
    small_gemm<<<dim3(MHH / 16, NN / 16), tb>>>(p_zq, Wq1, p_h1, NN, MHH, ZD, 0);
    small_gemm<<<dim3(MHH / 16, NN / 16), tb>>>(p_h1, Wq2, p_h2, NN, MHH, MHH, 0);
    small_gemm<<<dim3(HH * RR / 16, NN / 16), tb>>>(p_h2, Wq3, p_qb, NN, HH * RR, MHH, 1);
    small_gemm<<<dim3(MHH / 16, NN / 16), tb>>>(p_zk, Wk1, p_h1, NN, MHH, ZD, 0);
    small_gemm<<<dim3(MHH / 16, NN / 16), tb>>>(p_h1, Wk2, p_h2, NN, MHH, MHH, 0);
    small_gemm<<<dim3(HH * RR / 16, NN / 16), tb>>>(p_h2, Wk3, p_kb, NN, HH * RR, MHH, 1);

    // 4. low-rank bias matrix
    bias_outer_kernel<<<dim3(NN / 16, NN / 16, HH), tb>>>();

    // 5. projections on tensor cores (3xTF32)
    int gsmem = (128 * AS_S + 128 * WS_S) * sizeof(float);   // ~137 KB
    cudaFuncSetAttribute(tc_gemm, cudaFuncAttributeMaxDynamicSharedMemorySize, gsmem);
    int gblocks = NN * NN / 128;   // 1152
    tc_gemm<<<gblocks, 256, gsmem>>>(p_xn, nullptr, Wq_att, nullptr, p_q, 0);
    tc_gemm<<<gblocks, 256, gsmem>>>(p_xn, nullptr, Wk_att, nullptr, p_k, 1);
    tc_gemm<<<gblocks, 256, gsmem>>>(p_xn, nullptr, Wv_att, nullptr, p_v, 2);
    tc_gemm<<<gblocks, 256, gsmem>>>(p_xn, nullptr, Wg, bg, p_gate, 3);

    // 6. attention on tensor cores (3xTF32)
    int asmem = (64 * ST_S + 64 * 33 + 64) * sizeof(float);  // ~108 KB
    cudaFuncSetAttribute(attn_tc_kernel, cudaFuncAttributeMaxDynamicSharedMemorySize, asmem);
    attn_tc_kernel<<<dim3(NN / 64, HH, NN), 256, asmem>>>();

    // 7. gated output projection (tensor cores, gate fused into A load)
    tc_gemm<<<gblocks, 256, gsmem>>>(p_o, p_gate, Wo, bo, out, 4);
}

// round 17
// speedup vs baseline: 1.7218x; 1.0334x over previous
#include <cuda_runtime.h>
#include <math.h>
#include <stdint.h>

#define NN   384
#define CC   128
#define HH   4
#define DHH  32
#define RR   96
#define SD   449
#define ZD   577     // CC + SD
#define MHH  256
#define HD   128     // HH*DHH

#define AS_S 132     // tc_gemm As row stride
#define WS_S 136     // tc_gemm Ws row stride
#define ST_S 388     // attn scores row stride (388 % 32 == 4 -> conflict-free frag loads)

// ---------------- scratch (device globals; no allocation allowed) ----------------
__device__ float g_xn[(size_t)NN * NN * CC];     // layernormed x  [i][j][c]
__device__ float g_zq[NN * ZD];                  // concat(mean1, s_inputs)
__device__ float g_zk[NN * ZD];                  // concat(mean0, s_inputs)
__device__ float g_h1[NN * MHH];
__device__ float g_h2[NN * MHH];
__device__ float g_qb[HH * NN * RR];             // [h][n][r]
__device__ float g_kb[HH * NN * RR];
__device__ float g_bias[(size_t)HH * NN * NN];   // [h][q][k]
__device__ float g_q[(size_t)NN * HH * NN * DHH]; // [i][h][j][d]
__device__ float g_k[(size_t)NN * HH * NN * DHH];
__device__ float g_v[(size_t)NN * HH * NN * DHH];
__device__ float g_gate[(size_t)NN * NN * CC];   // [i][j][c]
__device__ float g_o[(size_t)NN * NN * CC];      // [i][j][h*DH+d]

// ---------------- LayerNorm: one warp per (i,j) vector of 128 ----------------
__global__ void ln_kernel(const float* __restrict__ x,
                          const float* __restrict__ gamma,
                          const float* __restrict__ beta) {
    int w = threadIdx.x >> 5, lane = threadIdx.x & 31;
    size_t ij = (size_t)blockIdx.x * 4 + w;
    const float4 v4 = *(const float4*)(x + ij * CC + lane * 4);
    float s  = v4.x + v4.y + v4.z + v4.w;
    float s2 = v4.x * v4.x + v4.y * v4.y + v4.z * v4.z + v4.w * v4.w;
    #pragma unroll
    for (int o = 16; o > 0; o >>= 1) {
        s  += __shfl_xor_sync(0xffffffffu, s,  o);
        s2 += __shfl_xor_sync(0xffffffffu, s2, o);
    }
    float m   = s * (1.0f / CC);
    float var = s2 * (1.0f / CC) - m * m;
    float r   = rsqrtf(var + 1e-5f);
    float4 g4 = *(const float4*)(gamma + lane * 4);
    float4 b4 = *(const float4*)(beta  + lane * 4);
    float4 o4;
    o4.x = (v4.x - m) * r * g4.x + b4.x;
    o4.y = (v4.y - m) * r * g4.y + b4.y;
    o4.z = (v4.z - m) * r * g4.z + b4.z;
    o4.w = (v4.w - m) * r * g4.w + b4.w;
    *(float4*)(g_xn + ij * CC + lane * 4) = o4;
}

// ---------------- fused means + s_inputs concat ----------------
__global__ void prep_kernel(const float* __restrict__ s_inputs) {
    int n = blockIdx.x;
    int t = threadIdx.x;
    if (t < CC) {                 // mean over j -> g_zq[n][0:128]
        const float* p = g_xn + (size_t)n * NN * CC + t;
        float s = 0.f;
        #pragma unroll 8
        for (int j = 0; j < NN; j++) s += p[(size_t)j * CC];
        g_zq[n * ZD + t] = s * (1.0f / NN);
    } else {                      // mean over i -> g_zk[n][0:128]
        int c = t - CC;
        const float* p = g_xn + (size_t)n * CC + c;
        float s = 0.f;
        #pragma unroll 8
        for (int i = 0; i < NN; i++) s += p[(size_t)i * NN * CC];
        g_zk[n * ZD + c] = s * (1.0f / NN);
    }
    for (int s = t; s < SD; s += blockDim.x) {
        float v = s_inputs[n * SD + s];
        g_zq[n * ZD + CC + s] = v;
        g_zk[n * ZD + CC + s] = v;
    }
}

// ---------------- small GEMM (bias MLPs): C = act(A[M,K] @ B[K,Nc]) ----------------
__global__ void small_gemm(const float* __restrict__ A, const float* __restrict__ B,
                           float* __restrict__ Cm, int M, int Nc, int K, int mode) {
    __shared__ float As[16][17], Bs[16][17];
    int row = blockIdx.y * 16 + threadIdx.y;
    int col = blockIdx.x * 16 + threadIdx.x;
    float acc = 0.f;
    for (int kt = 0; kt < K; kt += 16) {
        int ka = kt + threadIdx.x;
        As[threadIdx.y][threadIdx.x] = (row < M && ka < K) ? A[row * K + ka] : 0.f;
        int kb = kt + threadIdx.y;
        Bs[threadIdx.y][threadIdx.x] = (kb < K && col < Nc) ? B[kb * Nc + col] : 0.f;
        __syncthreads();
        #pragma unroll
        for (int kk = 0; kk < 16; kk++) acc += As[threadIdx.y][kk] * Bs[kk][threadIdx.x];
        __syncthreads();
    }
    if (row < M && col < Nc) {
        if (mode == 0) {
            Cm[row * Nc + col] = tanhf(acc);
        } else {
            int h = col / RR, r = col % RR;
            Cm[(h * NN + row) * RR + r] = acc;
        }
    }
}

// ---------------- low-rank bias: bias[h][q][k] = sum_r qb[h][q][r]*kb[h][k][r] ----------------
__global__ void bias_outer_kernel() {
    int h = blockIdx.z;
    int q = blockIdx.y * 16 + threadIdx.y;
    int k = blockIdx.x * 16 + threadIdx.x;
    __shared__ float Qs[16][17], Ks[16][17];
    const float* qb = g_qb + (size_t)h * NN * RR;
    const float* kb = g_kb + (size_t)h * NN * RR;
    float acc = 0.f;
    for (int rt = 0; rt < RR; rt += 16) {
        Qs[threadIdx.y][threadIdx.x] = qb[(blockIdx.y * 16 + threadIdx.y) * RR + rt + threadIdx.x];
        Ks[threadIdx.y][threadIdx.x] = kb[(blockIdx.x * 16 + threadIdx.y) * RR + rt + threadIdx.x];
        __syncthreads();
        #pragma unroll
        for (int kk = 0; kk < 16; kk++) acc += Qs[threadIdx.y][kk] * Ks[threadIdx.x][kk];
        __syncthreads();
    }
    g_bias[((size_t)h * NN + q) * NN + k] = acc;
}

// ---------------- 3xTF32 helpers ----------------
__device__ __forceinline__ void tf32_split(float a, uint32_t& hi, uint32_t& lo) {
    uint32_t b = __float_as_uint(a);
    hi = b & 0xFFFFE000u;                     // tf32 truncation (matches HW read)
    lo = __float_as_uint(a - __uint_as_float(hi));
}

#define MMA_TF32(acc, a, b)                                                     \
    asm volatile("mma.sync.aligned.m16n8k8.row.col.f32.tf32.tf32.f32 "          \
                 "{%0,%1,%2,%3}, {%4,%5,%6,%7}, {%8,%9}, {%0,%1,%2,%3};\n"      \
                 : "+f"((acc)[0]), "+f"((acc)[1]), "+f"((acc)[2]), "+f"((acc)[3]) \
                 : "r"((a)[0]), "r"((a)[1]), "r"((a)[2]), "r"((a)[3]),          \
                   "r"((b)[0]), "r"((b)[1]))

// ---------------- fused QKVG projection (3xTF32): A tile staged once, 4 weights ----------------
__global__ void __launch_bounds__(256) tc_gemm_qkvg(const float* __restrict__ Wq,
                                                    const float* __restrict__ Wk,
                                                    const float* __restrict__ Wv,
                                                    const float* __restrict__ Wg,
                                                    const float* __restrict__ bg) {
    extern __shared__ float sh[];
    float* As = sh;                     // [128][AS_S]
    float* Ws = sh + 128 * AS_S;        // [128][WS_S], k-major
    int t = threadIdx.x;
    size_t m0 = (size_t)blockIdx.x * 128;

    #pragma unroll
    for (int l = 0; l < 16; l++) {      // A tile 128x128 from g_xn
        int lin = t + l * 256;
        int m  = lin >> 5;
        int k4 = (lin & 31) << 2;
        float4 a4 = *(const float4*)(g_xn + (m0 + m) * CC + k4);
        float* dst = As + m * AS_S + k4;
        dst[0] = a4.x; dst[1] = a4.y; dst[2] = a4.z; dst[3] = a4.w;
    }

    int wid = t >> 5, lane = t & 31;
    int wm = (wid >> 1) * 32, wn = (wid & 1) * 64;
    int lr = lane >> 2, lc = lane & 3;
    const float qscale = 0.17677669529663687f;  // 1/sqrt(32)

    const float* Wlist[4] = {Wq, Wk, Wv, Wg};
    float* Olist[4] = {g_q, g_k, g_v, g_gate};

    for (int w = 0; w < 4; w++) {
        const float* W = Wlist[w];
        #pragma unroll
        for (int l = 0; l < 16; l++) {   // stage W (L2-resident after first block)
            int lin = t + l * 256;
            int k  = lin >> 5;
            int n4 = (lin & 31) << 2;
            float4 w4 = *(const float4*)(W + k * HD + n4);
            float* dst = Ws + k * WS_S + n4;
            dst[0] = w4.x; dst[1] = w4.y; dst[2] = w4.z; dst[3] = w4.w;
        }
        __syncthreads();

        float acc[2][8][4];
        #pragma unroll
        for (int a = 0; a < 2; a++)
            #pragma unroll
            for (int b = 0; b < 8; b++)
                #pragma unroll
                for (int e = 0; e < 4; e++) acc[a][b][e] = 0.f;

        for (int k0 = 0; k0 < CC; k0 += 8) {
            uint32_t ahi[2][4], alo[2][4];
            #pragma unroll
            for (int tm = 0; tm < 2; tm++) {
                int r0 = wm + tm * 16 + lr;
                tf32_split(As[r0 * AS_S + k0 + lc],           ahi[tm][0], alo[tm][0]);
                tf32_split(As[(r0 + 8) * AS_S + k0 + lc],     ahi[tm][1], alo[tm][1]);
                tf32_split(As[r0 * AS_S + k0 + lc + 4],       ahi[tm][2], alo[tm][2]);
                tf32_split(As[(r0 + 8) * AS_S + k0 + lc + 4], ahi[tm][3], alo[tm][3]);
            }
            uint32_t bhi[8][2], blo[8][2];
            #pragma unroll
            for (int tn = 0; tn < 8; tn++) {
                int n = wn + tn * 8 + lr;
                tf32_split(Ws[(k0 + lc) * WS_S + n],     bhi[tn][0], blo[tn][0]);
                tf32_split(Ws[(k0 + lc + 4) * WS_S + n], bhi[tn][1], blo[tn][1]);
            }
            #pragma unroll
            for (int tm = 0; tm < 2; tm++)
                #pragma unroll
                for (int tn = 0; tn < 8; tn++) {
                    MMA_TF32(acc[tm][tn], ahi[tm], bhi[tn]);
                    MMA_TF32(acc[tm][tn], ahi[tm], blo[tn]);
                    MMA_TF32(acc[tm][tn], alo[tm], bhi[tn]);
                }
        }

        float* out = Olist[w];
        #pragma unroll
        for (int tm = 0; tm < 2; tm++) {
            #pragma unroll
            for (int tn = 0; tn < 8; tn++) {
                #pragma unroll
                for (int e = 0; e < 4; e++) {
                    int row = wm + tm * 16 + lr + ((e >> 1) ? 8 : 0);
                    int col = wn + tn * 8 + lc * 2 + (e & 1);
                    size_t m = m0 + row;
                    float v = acc[tm][tn][e];
                    if (w <= 2) {
                        int i = (int)(m / NN), j = (int)(m % NN);
                        int h = col / DHH, d = col % DHH;
                        if (w == 0) v *= qscale;
                        out[(((size_t)i * HH + h) * NN + j) * DHH + d] = v;
                    } else {
                        v += bg[col];
                        out[m * CC + col] = 1.0f / (1.0f + __expf(-v));
                    }
                }
            }
        }
        __syncthreads();   // compute (Ws reads) done before restage
    }
}

// ---------------- final gated projection (3xTF32): out = (gate*o) @ Wo + bo ----------------
__global__ void __launch_bounds__(256) tc_gemm_out(const float* __restrict__ Wo,
                                                   const float* __restrict__ bo,
                                                   float* __restrict__ out) {
    extern __shared__ float sh[];
    float* As = sh;
    float* Ws = sh + 128 * AS_S;
    int t = threadIdx.x;
    size_t m0 = (size_t)blockIdx.x * 128;

    #pragma unroll
    for (int l = 0; l < 16; l++) {
        int lin = t + l * 256;
        int k  = lin >> 5;
        int n4 = (lin & 31) << 2;
        float4 w4 = *(const float4*)(Wo + k * HD + n4);
        float* dst = Ws + k * WS_S + n4;
        dst[0] = w4.x; dst[1] = w4.y; dst[2] = w4.z; dst[3] = w4.w;
    }
    #pragma unroll
    for (int l = 0; l < 16; l++) {
        int lin = t + l * 256;
        int m  = lin >> 5;
        int k4 = (lin & 31) << 2;
        size_t off = (m0 + m) * CC + k4;
        float4 a4 = *(const float4*)(g_o + off);
        float4 g4 = *(const float4*)(g_gate + off);
        a4.x *= g4.x; a4.y *= g4.y; a4.z *= g4.z; a4.w *= g4.w;
        float* dst = As + m * AS_S + k4;
        dst[0] = a4.x; dst[1] = a4.y; dst[2] = a4.z; dst[3] = a4.w;
    }
    __syncthreads();

    int wid = t >> 5, lane = t & 31;
    int wm = (wid >> 1) * 32, wn = (wid & 1) * 64;
    int lr = lane >> 2, lc = lane & 3;

    float acc[2][8][4];
    #pragma unroll
    for (int a = 0; a < 2; a++)
        #pragma unroll
        for (int b = 0; b < 8; b++)
            #pragma unroll
            for (int e = 0; e < 4; e++) acc[a][b][e] = 0.f;

    for (int k0 = 0; k0 < CC; k0 += 8) {
        uint32_t ahi[2][4], alo[2][4];
        #pragma unroll
        for (int tm = 0; tm < 2; tm++) {
            int r0 = wm + tm * 16 + lr;
            tf32_split(As[r0 * AS_S + k0 + lc],           ahi[tm][0], alo[tm][0]);
            tf32_split(As[(r0 + 8) * AS_S + k0 + lc],     ahi[tm][1], alo[tm][1]);
            tf32_split(As[r0 * AS_S + k0 + lc + 4],       ahi[tm][2], alo[tm][2]);
            tf32_split(As[(r0 + 8) * AS_S + k0 + lc + 4], ahi[tm][3], alo[tm][3]);
        }
        uint32_t bhi[8][2], blo[8][2];
        #pragma unroll
        for (int tn = 0; tn < 8; tn++) {
            int n = wn + tn * 8 + lr;
            tf32_split(Ws[(k0 + lc) * WS_S + n],     bhi[tn][0], blo[tn][0]);
            tf32_split(Ws[(k0 + lc + 4) * WS_S + n], bhi[tn][1], blo[tn][1]);
        }
        #pragma unroll
        for (int tm = 0; tm < 2; tm++)
            #pragma unroll
            for (int tn = 0; tn < 8; tn++) {
                MMA_TF32(acc[tm][tn], ahi[tm], bhi[tn]);
                MMA_TF32(acc[tm][tn], ahi[tm], blo[tn]);
                MMA_TF32(acc[tm][tn], alo[tm], bhi[tn]);
            }
    }

    #pragma unroll
    for (int tm = 0; tm < 2; tm++)
        #pragma unroll
        for (int tn = 0; tn < 8; tn++)
            #pragma unroll
            for (int e = 0; e < 4; e++) {
                int row = wm + tm * 16 + lr + ((e >> 1) ? 8 : 0);
                int col = wn + tn * 8 + lc * 2 + (e & 1);
                out[(m0 + row) * CC + col] = acc[tm][tn][e] + bo[col];
            }
}

// ---------------- tensor-core attention with register-prefetch pipelining ----------------
__global__ void __launch_bounds__(256) attn_tc_kernel() {
    extern __shared__ float sm[];
    float* st    = sm;                 // [64][ST_S]
    float* kvb   = st + 64 * ST_S;     // [64][33] staging for Q, K, V chunks
    float* sminv = kvb + 64 * 33;      // [64]

    int q0 = blockIdx.x * 64;
    int h  = blockIdx.y;
    int i  = blockIdx.z;
    int t  = threadIdx.x;
    int wid = t >> 5, lane = t & 31;
    int lr = lane >> 2, lc = lane & 3;

    size_t base = ((size_t)i * HH + h) * NN * DHH;
    const float* qg = g_q + base + (size_t)q0 * DHH;
    const float* kg = g_k + base;
    const float* vg = g_v + base;
    const float* biasrow = g_bias + (size_t)h * NN * NN;

    int r_s = t >> 3, d4_s = (t & 7) << 2;        // staging coords (thread -> row, 4 floats)
    int r_s2 = r_s + 32;                          // second half (t+256)

    // ---- stage Q ----
    {
        float4 v0 = *(const float4*)(qg + (size_t)r_s * DHH + d4_s);
        float4 v1 = *(const float4*)(qg + (size_t)r_s2 * DHH + d4_s);
        float* d0 = &kvb[r_s * 33 + d4_s];
        d0[0] = v0.x; d0[1] = v0.y; d0[2] = v0.z; d0[3] = v0.w;
        float* d1 = &kvb[r_s2 * 33 + d4_s];
        d1[0] = v1.x; d1[1] = v1.y; d1[2] = v1.z; d1[3] = v1.w;
    }
    // prefetch K chunk 0 while Q lands
    float4 pre0 = *(const float4*)(kg + (size_t)r_s * DHH + d4_s);
    float4 pre1 = *(const float4*)(kg + (size_t)r_s2 * DHH + d4_s);
    __syncthreads();

    int wr = wid >> 1;        // q sub-tile (4 x 16 rows)
    int wc = wid & 1;         // phase1: k-col half; phase2: d half
    uint32_t qhi[4][4], qlo[4][4];
    {
        int r0 = wr * 16 + lr;
        #pragma unroll
        for (int ks = 0; ks < 4; ks++) {
            tf32_split(kvb[r0 * 33 + ks * 8 + lc],           qhi[ks][0], qlo[ks][0]);
            tf32_split(kvb[(r0 + 8) * 33 + ks * 8 + lc],     qhi[ks][1], qlo[ks][1]);
            tf32_split(kvb[r0 * 33 + ks * 8 + lc + 4],       qhi[ks][2], qlo[ks][2]);
            tf32_split(kvb[(r0 + 8) * 33 + ks * 8 + lc + 4], qhi[ks][3], qlo[ks][3]);
        }
    }

    // ---- phase 1: scores (K chunk c in regs before barrier; next chunk LDG overlaps MMA) ----
    for (int c = 0; c < 6; c++) {
        __syncthreads();                      // prior kvb readers done
        {
            float* d0 = &kvb[r_s * 33 + d4_s];
            d0[0] = pre0.x; d0[1] = pre0.y; d0[2] = pre0.z; d0[3] = pre0.w;
            float* d1 = &kvb[r_s2 * 33 + d4_s];
            d1[0] = pre1.x; d1[1] = pre1.y; d1[2] = pre1.z; d1[3] = pre1.w;
        }
        if (c < 5) {                          // prefetch next K chunk
            const float* src = kg + (size_t)(c + 1) * 64 * DHH;
            pre0 = *(const float4*)(src + (size_t)r_s * DHH + d4_s);
            pre1 = *(const float4*)(src + (size_t)r_s2 * DHH + d4_s);
        } else {                              // prefetch V chunk 0 (hidden under softmax)
            pre0 = *(const float4*)(vg + (size_t)r_s * DHH + d4_s);
            pre1 = *(const float4*)(vg + (size_t)r_s2 * DHH + d4_s);
        }
        __syncthreads();

        int kc = c * 64;
        float acc[4][4];
        #pragma unroll
        for (int tn = 0; tn < 4; tn++)
            #pragma unroll
            for (int e = 0; e < 4; e++) acc[tn][e] = 0.f;
        #pragma unroll
        for (int ks = 0; ks < 4; ks++) {
            #pragma unroll
            for (int tn = 0; tn < 4; tn++) {
                int n = wc * 32 + tn * 8 + lr;
                uint32_t bhi[2], blo[2];
                tf32_split(kvb[n * 33 + ks * 8 + lc],     bhi[0], blo[0]);
                tf32_split(kvb[n * 33 + ks * 8 + lc + 4], bhi[1], blo[1]);
                MMA_TF32(acc[tn], qhi[ks], bhi);
                MMA_TF32(acc[tn], qhi[ks], blo);
                MMA_TF32(acc[tn], qlo[ks], bhi);
            }
        }
        #pragma unroll
        for (int tn = 0; tn < 4; tn++)
            #pragma unroll
            for (int e = 0; e < 4; e++) {
                int row = wr * 16 + lr + ((e >> 1) ? 8 : 0);
                int col = kc + wc * 32 + tn * 8 + lc * 2 + (e & 1);
                st[row * ST_S + col] = acc[tn][e];
            }
    }
    __syncthreads();

    // ---- softmax over 384 cols (bias fused; warp handles 8 rows) ----
    #pragma unroll
    for (int rr = 0; rr < 8; rr++) {
        int row = wid * 8 + rr;
        const float* brow = biasrow + (size_t)(q0 + row) * NN;
        float vals[12];
        float mx = -1e30f;
        #pragma unroll
        for (int m = 0; m < 12; m++) {
            vals[m] = st[row * ST_S + lane + m * 32] + brow[lane + m * 32];
            mx = fmaxf(mx, vals[m]);
        }
        #pragma unroll
        for (int o = 16; o > 0; o >>= 1) mx = fmaxf(mx, __shfl_xor_sync(0xffffffffu, mx, o));
        float s = 0.f;
        #pragma unroll
        for (int m = 0; m < 12; m++) {
            float p = __expf(vals[m] - mx);
            st[row * ST_S + lane + m * 32] = p;
            s += p;
        }
        #pragma unroll
        for (int o = 16; o > 0; o >>= 1) s += __shfl_xor_sync(0xffffffffu, s, o);
        if (lane == 0) sminv[row] = 1.0f / s;
    }

    // ---- phase 2: O = P V (V chunk prefetched in regs) ----
    float oacc[2][4];
    #pragma unroll
    for (int tn = 0; tn < 2; tn++)
        #pragma unroll
        for (int e = 0; e < 4; e++) oacc[tn][e] = 0.f;

    for (int c = 0; c < 6; c++) {
        __syncthreads();                      // softmax / prior compute done
        {
            float* d0 = &kvb[r_s * 33 + d4_s];
            d0[0] = pre0.x; d0[1] = pre0.y; d0[2] = pre0.z; d0[3] = pre0.w;
            float* d1 = &kvb[r_s2 * 33 + d4_s];
            d1[0] = pre1.x; d1[1] = pre1.y; d1[2] = pre1.z; d1[3] = pre1.w;
        }
        if (c < 5) {
            const float* src = vg + (size_t)(c + 1) * 64 * DHH;
            pre0 = *(const float4*)(src + (size_t)r_s * DHH + d4_s);
            pre1 = *(const float4*)(src + (size_t)r_s2 * DHH + d4_s);
        }
        __syncthreads();

        int kc = c * 64;
        int r0 = wr * 16 + lr;
        #pragma unroll
        for (int ks = 0; ks < 8; ks++) {
            uint32_t ahi[4], alo[4];
            int k0 = kc + ks * 8;
            tf32_split(st[r0 * ST_S + k0 + lc],           ahi[0], alo[0]);
            tf32_split(st[(r0 + 8) * ST_S + k0 + lc],     ahi[1], alo[1]);
            tf32_split(st[r0 * ST_S + k0 + lc + 4],       ahi[2], alo[2]);
            tf32_split(st[(r0 + 8) * ST_S + k0 + lc + 4], ahi[3], alo[3]);
            #pragma unroll
            for (int tn = 0; tn < 2; tn++) {
                int n = wc * 16 + tn * 8 + lr;
                uint32_t bhi[2], blo[2];
                tf32_split(kvb[(ks * 8 + lc) * 33 + n],     bhi[0], blo[0]);
                tf32_split(kvb[(ks * 8 + lc + 4) * 33 + n], bhi[1], blo[1]);
                MMA_TF32(oacc[tn], ahi, bhi);
                MMA_TF32(oacc[tn], ahi, blo);
                MMA_TF32(oacc[tn], alo, bhi);
            }
        }
    }

    #pragma unroll
    for (int tn = 0; tn < 2; tn++)
        #pragma unroll
        for (int e = 0; e < 4; e++) {
            int row = wr * 16 + lr + ((e >> 1) ? 8 : 0);
            int d   = wc * 16 + tn * 8 + lc * 2 + (e & 1);
            g_o[((size_t)i * NN + q0 + row) * CC + h * DHH + d] = oacc[tn][e] * sminv[row];
        }
}

// ---------------- launch ----------------
extern "C" void kernel_launch(void* const* d_in, const int* in_sizes, int n_in,
                              void* d_out, int out_size) {
    const float* x        = (const float*)d_in[0];
    const float* s_inputs = (const float*)d_in[1];
    const float* ln_gamma = (const float*)d_in[2];
    const float* ln_beta  = (const float*)d_in[3];
    const float* Wq1      = (const float*)d_in[4];
    const float* Wq2      = (const float*)d_in[5];
    const float* Wq3      = (const float*)d_in[6];
    const float* Wk1      = (const float*)d_in[7];
    const float* Wk2      = (const float*)d_in[8];
    const float* Wk3      = (const float*)d_in[9];
    const float* Wq_att   = (const float*)d_in[10];
    const float* Wk_att   = (const float*)d_in[11];
    const float* Wv_att   = (const float*)d_in[12];
    const float* Wg       = (const float*)d_in[13];
    const float* bg       = (const float*)d_in[14];
    const float* Wo       = (const float*)d_in[15];
    const float* bo       = (const float*)d_in[16];
    float* out = (float*)d_out;

    void *p_zq_v = nullptr, *p_zk_v = nullptr, *p_h1_v = nullptr, *p_h2_v = nullptr;
    void *p_qb_v = nullptr, *p_kb_v = nullptr;
    cudaGetSymbolAddress(&p_zq_v, g_zq);
    cudaGetSymbolAddress(&p_zk_v, g_zk);
    cudaGetSymbolAddress(&p_h1_v, g_h1);
    cudaGetSymbolAddress(&p_h2_v, g_h2);
    cudaGetSymbolAddress(&p_qb_v, g_qb);
    cudaGetSymbolAddress(&p_kb_v, g_kb);
    float* p_zq = (float*)p_zq_v;
    float* p_zk = (float*)p_zk_v;
    float* p_h1 = (float*)p_h1_v;
    float* p_h2 = (float*)p_h2_v;
    float* p_qb = (float*)p_qb_v;
    float* p_kb = (float*)p_kb_v;

    // 1. LayerNorm
    ln_kernel<<<NN * NN / 4, 128>>>(x, ln_gamma, ln_beta);

    // 2. means + concat (fused)
    prep_kernel<<<NN, 256>>>(s_inputs);

    // 3. bias MLPs
    dim3 tb(16, 16);
    small_gemm<<<dim3(MHH / 16, NN / 16), tb>>>(p_zq, Wq1, p_h1, NN, MHH, ZD, 0);
    small_gemm<<<dim3(MHH / 16, NN / 16), tb>>>(p_h1, Wq2, p_h2, NN, MHH, MHH, 0);
    small_gemm<<<dim3(HH * RR / 16, NN / 16), tb>>>(p_h2, Wq3, p_qb, NN, HH * RR, MHH, 1);
    small_gemm<<<dim3(MHH / 16, NN / 16), tb>>>(p_zk, Wk1, p_h1, NN, MHH, ZD, 0);
    small_gemm<<<dim3(MHH / 16, NN / 16), tb>>>(p_h1, Wk2, p_h2, NN, MHH, MHH, 0);
    small_gemm<<<dim3(HH * RR / 16, NN / 16), tb>>>(p_h2, Wk3, p_kb, NN, HH * RR, MHH, 1);

    // 4. low-rank bias matrix
    bias_outer_kernel<<<dim3(NN / 16, NN / 16, HH), tb>>>();

    // 5. fused Q/K/V/gate projections (A tile staged once)
    int gsmem = (128 * AS_S + 128 * WS_S) * sizeof(float);   // ~137 KB
    cudaFuncSetAttribute(tc_gemm_qkvg, cudaFuncAttributeMaxDynamicSharedMemorySize, gsmem);
    cudaFuncSetAttribute(tc_gemm_out,  cudaFuncAttributeMaxDynamicSharedMemorySize, gsmem);
    int gblocks = NN * NN / 128;   // 1152
    tc_gemm_qkvg<<<gblocks, 256, gsmem>>>(Wq_att, Wk_att, Wv_att, Wg, bg);

    // 6. attention on tensor cores (pipelined staging)
    int asmem = (64 * ST_S + 64 * 33 + 64) * sizeof(float);  // ~108 KB
    cudaFuncSetAttribute(attn_tc_kernel, cudaFuncAttributeMaxDynamicSharedMemorySize, asmem);
    attn_tc_kernel<<<dim3(NN / 64, HH, NN), 256, asmem>>>();

    // 7. gated output projection
    tc_gemm_out<<<gblocks, 256, gsmem>>>(Wo, bo, out);
}